// round 2
// baseline (speedup 1.0000x reference)
#include <cuda_runtime.h>

// Integrate-and-fire, hard reset, scanned over time axis.
// x: [T=32, N] float32, out: [T=32, N] float32 (spikes 0/1).
// N = 32*128*32*32 = 4,194,304. Each thread owns 4 neurons (float4),
// carries membrane potential in registers across the T loop.

#define T_STEPS 32
#define V_TH 1.0f

__global__ __launch_bounds__(256) void if_scan_kernel(
    const float4* __restrict__ x,
    float4* __restrict__ out,
    int n4)
{
    int i = blockIdx.x * blockDim.x + threadIdx.x;
    if (i >= n4) return;

    float mx = 0.0f, my = 0.0f, mz = 0.0f, mw = 0.0f;

    #pragma unroll
    for (int t = 0; t < T_STEPS; t++) {
        size_t idx = (size_t)t * n4 + i;
        float4 xt = __ldcs(&x[idx]);

        mx += xt.x; my += xt.y; mz += xt.z; mw += xt.w;

        float4 s;
        s.x = (mx >= V_TH) ? 1.0f : 0.0f;
        s.y = (my >= V_TH) ? 1.0f : 0.0f;
        s.z = (mz >= V_TH) ? 1.0f : 0.0f;
        s.w = (mw >= V_TH) ? 1.0f : 0.0f;

        // hard reset where spiked
        mx = (s.x != 0.0f) ? 0.0f : mx;
        my = (s.y != 0.0f) ? 0.0f : my;
        mz = (s.z != 0.0f) ? 0.0f : mz;
        mw = (s.w != 0.0f) ? 0.0f : mw;

        __stcs(&out[idx], s);
    }
}

extern "C" void kernel_launch(void* const* d_in, const int* in_sizes, int n_in,
                              void* d_out, int out_size)
{
    const float* x = (const float*)d_in[0];
    float* out = (float*)d_out;

    int total = in_sizes[0];          // T * N
    int n = total / T_STEPS;          // neurons
    int n4 = n / 4;                   // float4 lanes

    int threads = 256;
    int blocks = (n4 + threads - 1) / threads;

    if_scan_kernel<<<blocks, threads>>>(
        (const float4*)x, (float4*)out, n4);
}